// round 13
// baseline (speedup 1.0000x reference)
#include <cuda_runtime.h>

#define VOCAB 50000
#define EDIM  128
#define HDIM  15
#define CDIM  20
#define BATCH 512
#define SEQ   512
#define WP    132            // padded W_ih smem pitch (floats)

typedef unsigned long long ull;

// G table: [v][j] = {0.5*(r+bhh_r), 0.5*(z+bhh_z), n_part, 0}
__device__ float4 g_G[(size_t)VOCAB * 16];
__device__ int    g_xo[BATCH * SEQ];     // pre-clamped, pre-scaled row offsets (v*16)

__device__ __forceinline__ float tanhap(float x) {
    float y;
    asm("tanh.approx.f32 %0, %1;" : "=f"(y) : "f"(x));
    return y;
}
__device__ __forceinline__ int clampv(int v) { return min(max(v, 0), VOCAB - 1); }

__device__ __forceinline__ ull pk(float lo, float hi) {
    ull r; asm("mov.b64 %0, {%1, %2};" : "=l"(r) : "f"(lo), "f"(hi)); return r;
}
__device__ __forceinline__ void upk(float& lo, float& hi, ull v) {
    asm("mov.b64 {%0, %1}, %2;" : "=f"(lo), "=f"(hi) : "l"(v));
}
__device__ __forceinline__ ull f2fma(ull a, ull b, ull c) {
    ull d; asm("fma.rn.f32x2 %0, %1, %2, %3;" : "=l"(d) : "l"(a), "l"(b), "l"(c)); return d;
}
__device__ __forceinline__ ull f2add(ull a, ull b) {
    ull d; asm("add.rn.f32x2 %0, %1, %2;" : "=l"(d) : "l"(a), "l"(b)); return d;
}

// ---------------------------------------------------------------------------
// Kernel A: tiled gates GEMM + fused token conversion (first 256 blocks).
// Token conversion also clamps and scales: g_xo = clamp(v)*16.
// ---------------------------------------------------------------------------
__global__ void __launch_bounds__(256) gates_kernel(const float* __restrict__ embed,
                                                    const float* __restrict__ W_ih,
                                                    const float* __restrict__ b_ih,
                                                    const float* __restrict__ b_hh,
                                                    const void*  __restrict__ xraw) {
    if (blockIdx.x < 256) {
        __shared__ int s64;
        if (threadIdx.x == 0) {
            const int* xi = (const int*)xraw;
            int ok = 1;
            #pragma unroll
            for (int k = 0; k < 32; ++k)
                if (xi[2 * k + 1] != 0) ok = 0;   // int64 < 2^31 => high words 0
            s64 = ok;
        }
        __syncthreads();
        int i0 = (blockIdx.x * 256 + threadIdx.x) * 4;
        int4 o;
        if (s64) {
            const longlong4 v = ((const longlong4*)xraw)[i0 >> 2];
            o.x = (int)v.x; o.y = (int)v.y; o.z = (int)v.z; o.w = (int)v.w;
        } else {
            o = *(const int4*)((const int*)xraw + i0);
        }
        o.x = clampv(o.x) * 16; o.y = clampv(o.y) * 16;
        o.z = clampv(o.z) * 16; o.w = clampv(o.w) * 16;
        *(int4*)&g_xo[i0] = o;
    }

    // ---- gates GEMM ----
    __shared__ __align__(16) float Wsm[45 * WP];
    for (int i = threadIdx.x; i < 45 * EDIM; i += 256) {
        int r = i >> 7, c = i & 127;
        Wsm[r * WP + c] = W_ih[i];
    }
    __syncthreads();

    int rr = threadIdx.x >> 4;
    int ss = threadIdx.x & 15;
    int sw = min(ss, 14);
    int v0 = blockIdx.x * 64;

    const float4* w0p = (const float4*)&Wsm[sw * WP];
    const float4* w1p = (const float4*)&Wsm[(15 + sw) * WP];
    const float4* w2p = (const float4*)&Wsm[(30 + sw) * WP];

    const float4* ep[4];
    int vr[4];
    #pragma unroll
    for (int i = 0; i < 4; ++i) {
        vr[i] = v0 + rr + 16 * i;
        ep[i] = (const float4*)embed + (size_t)min(vr[i], VOCAB - 1) * 32;
    }

    float ar[4] = {0, 0, 0, 0}, az[4] = {0, 0, 0, 0}, an[4] = {0, 0, 0, 0};
    #pragma unroll 4
    for (int k4 = 0; k4 < 32; ++k4) {
        float4 w0 = w0p[k4], w1 = w1p[k4], w2 = w2p[k4];
        #pragma unroll
        for (int i = 0; i < 4; ++i) {
            float4 a = ep[i][k4];
            ar[i] = fmaf(a.x, w0.x, ar[i]); ar[i] = fmaf(a.y, w0.y, ar[i]);
            ar[i] = fmaf(a.z, w0.z, ar[i]); ar[i] = fmaf(a.w, w0.w, ar[i]);
            az[i] = fmaf(a.x, w1.x, az[i]); az[i] = fmaf(a.y, w1.y, az[i]);
            az[i] = fmaf(a.z, w1.z, az[i]); az[i] = fmaf(a.w, w1.w, az[i]);
            an[i] = fmaf(a.x, w2.x, an[i]); an[i] = fmaf(a.y, w2.y, an[i]);
            an[i] = fmaf(a.z, w2.z, an[i]); an[i] = fmaf(a.w, w2.w, an[i]);
        }
    }

    float bi0 = b_ih[sw] + b_hh[sw];               // fold b_hh into r,z slots
    float bi1 = b_ih[15 + sw] + b_hh[15 + sw];
    float bi2 = b_ih[30 + sw];
    #pragma unroll
    for (int i = 0; i < 4; ++i) {
        if (vr[i] < VOCAB) {
            float4 o;
            o.x = 0.5f * (ar[i] + bi0);            // pre-halved for sigmoid-via-tanh
            o.y = 0.5f * (az[i] + bi1);
            o.z = an[i] + bi2;
            o.w = 0.f;
            if (ss == 15) o = make_float4(0.f, 0.f, 0.f, 0.f);
            g_G[(size_t)vr[i] * 16 + ss] = o;
        }
    }
}

// ---------------------------------------------------------------------------
// Kernel B: GRU recurrence + fused head.
// 16 lanes/chain, 8 chains/block, ring-8 prefetch.
// Matvec: h pairs read straight from smem as LDS.64 (packed, zero movs) and
// consumed by fma.rn.f32x2 with pre-packed weights; G/bias terms folded into
// the accumulator initializers.
// ---------------------------------------------------------------------------
__global__ void __launch_bounds__(128, 1) rnn_kernel(const float* __restrict__ W_hh,
                                                     const float* __restrict__ b_hh,
                                                     const float* __restrict__ W_out,
                                                     const float* __restrict__ b_out,
                                                     float* __restrict__ out) {
    __shared__ __align__(16) float sh[8][2][16];
    const unsigned FULL = 0xffffffffu;
    int chain = threadIdx.x >> 4;
    int j     = threadIdx.x & 15;
    int jj    = min(j, 14);
    int gid   = blockIdx.x * 8 + chain;

    // pre-packed weight pairs (k=15 slot zero)
    ull wrp[8], wzp[8], wnp[8];
    {
        float wrf[16], wzf[16], wnf[16];
        #pragma unroll
        for (int k = 0; k < 15; ++k) {
            wrf[k] = 0.5f * W_hh[jj * 15 + k];     // pre-halved (sigmoid-via-tanh)
            wzf[k] = 0.5f * W_hh[(15 + jj) * 15 + k];
            wnf[k] = W_hh[(30 + jj) * 15 + k];
        }
        wrf[15] = wzf[15] = wnf[15] = 0.f;
        #pragma unroll
        for (int p = 0; p < 8; ++p) {
            wrp[p] = pk(wrf[2 * p], wrf[2 * p + 1]);
            wzp[p] = pk(wzf[2 * p], wzf[2 * p + 1]);
            wnp[p] = pk(wnf[2 * p], wnf[2 * p + 1]);
        }
    }
    const ull bn2 = pk(b_hh[30 + jj], 0.f);

    const int* xo = g_xo + (size_t)gid * SEQ;
    const float4* G4 = g_G;

    float4 ring[8];
    #pragma unroll
    for (int i = 0; i < 8; ++i)
        ring[i] = G4[xo[i] + j];

    const ull* hp = (const ull*)&sh[chain][0][0];  // 8 pairs per phase (16 floats)

    float h = 0.f;
    for (int s0 = 0; s0 < SEQ; s0 += 8) {
        #pragma unroll
        for (int u = 0; u < 8; ++u) {
            int s = s0 + u;
            float4 gc = ring[u];
            int pf = (s + 8 < SEQ) ? s + 8 : SEQ - 1;
            ring[u] = G4[xo[pf] + j];              // refill 8 steps ahead

            int p = s & 1;
            sh[chain][p][j] = h;
            __syncwarp(FULL);
            const ull* hb = hp + p * 8;
            ull h0 = hb[0], h1 = hb[1], h2 = hb[2], h3 = hb[3];
            ull h4 = hb[4], h5 = hb[5], h6 = hb[6], h7 = hb[7];

            // gate pre-activations folded into accumulator inits
            ull ra0 = pk(gc.x, 0.f), ra1 = 0;
            ull za0 = pk(gc.y, 0.f), za1 = 0;
            ull na0 = bn2,           na1 = 0;
            ra0 = f2fma(wrp[0], h0, ra0); ra1 = f2fma(wrp[1], h1, ra1);
            za0 = f2fma(wzp[0], h0, za0); za1 = f2fma(wzp[1], h1, za1);
            na0 = f2fma(wnp[0], h0, na0); na1 = f2fma(wnp[1], h1, na1);
            ra0 = f2fma(wrp[2], h2, ra0); ra1 = f2fma(wrp[3], h3, ra1);
            za0 = f2fma(wzp[2], h2, za0); za1 = f2fma(wzp[3], h3, za1);
            na0 = f2fma(wnp[2], h2, na0); na1 = f2fma(wnp[3], h3, na1);
            ra0 = f2fma(wrp[4], h4, ra0); ra1 = f2fma(wrp[5], h5, ra1);
            za0 = f2fma(wzp[4], h4, za0); za1 = f2fma(wzp[5], h5, za1);
            na0 = f2fma(wnp[4], h4, na0); na1 = f2fma(wnp[5], h5, na1);
            ra0 = f2fma(wrp[6], h6, ra0); ra1 = f2fma(wrp[7], h7, ra1);
            za0 = f2fma(wzp[6], h6, za0); za1 = f2fma(wzp[7], h7, za1);
            na0 = f2fma(wnp[6], h6, na0); na1 = f2fma(wnp[7], h7, na1);

            float rl, rh2, zl, zh2, nl, nh2;
            upk(rl, rh2, f2add(ra0, ra1));
            upk(zl, zh2, f2add(za0, za1));
            upk(nl, nh2, f2add(na0, na1));

            float rg = fmaf(0.5f, tanhap(rl + rh2), 0.5f);
            float zg = fmaf(0.5f, tanhap(zl + zh2), 0.5f);
            float ng = tanhap(fmaf(rg, nl + nh2, gc.z));
            h = fmaf(zg, h - ng, ng);              // (1-z)*n + z*h
        }
    }

    // ---- fused head: final h exchange + logits + softmax over 20 classes ----
    sh[chain][0][j] = h;
    __syncwarp(FULL);
    float hh[15];
    {
        float4 H0 = *(const float4*)&sh[chain][0][0];
        float4 H1 = *(const float4*)&sh[chain][0][4];
        float4 H2 = *(const float4*)&sh[chain][0][8];
        float4 H3 = *(const float4*)&sh[chain][0][12];
        hh[0]=H0.x; hh[1]=H0.y; hh[2]=H0.z; hh[3]=H0.w;
        hh[4]=H1.x; hh[5]=H1.y; hh[6]=H1.z; hh[7]=H1.w;
        hh[8]=H2.x; hh[9]=H2.y; hh[10]=H2.z; hh[11]=H2.w;
        hh[12]=H3.x; hh[13]=H3.y; hh[14]=H3.z;
    }
    float l0 = b_out[j];
    float l1 = (j < 4) ? b_out[16 + j] : -3.0e38f;
    #pragma unroll
    for (int k = 0; k < 15; ++k) {
        l0 = fmaf(W_out[j * 15 + k], hh[k], l0);
        if (j < 4) l1 = fmaf(W_out[(16 + j) * 15 + k], hh[k], l1);
    }
    float m = fmaxf(l0, l1);
    #pragma unroll
    for (int o = 8; o > 0; o >>= 1) m = fmaxf(m, __shfl_xor_sync(FULL, m, o, 16));
    float e0 = __expf(l0 - m);
    float e1 = (j < 4) ? __expf(l1 - m) : 0.f;
    float sum = e0 + e1;
    #pragma unroll
    for (int o = 8; o > 0; o >>= 1) sum += __shfl_xor_sync(FULL, sum, o, 16);
    float inv = __fdividef(1.f, sum);
    out[gid * CDIM + j] = e0 * inv;
    if (j < 4) out[gid * CDIM + 16 + j] = e1 * inv;
}

// ---------------------------------------------------------------------------
extern "C" void kernel_launch(void* const* d_in, const int* in_sizes, int n_in,
                              void* d_out, int out_size) {
    const void*  x     = d_in[0];
    const float* embed = (const float*)d_in[1];
    const float* W_ih  = (const float*)d_in[2];
    const float* b_ih  = (const float*)d_in[3];
    const float* W_hh  = (const float*)d_in[4];
    const float* b_hh  = (const float*)d_in[5];
    const float* W_out = (const float*)d_in[6];
    const float* b_out = (const float*)d_in[7];
    float* out = (float*)d_out;

    gates_kernel<<<(VOCAB + 63) / 64, 256>>>(embed, W_ih, b_ih, b_hh, x);
    rnn_kernel<<<BATCH / 8, 128>>>(W_hh, b_hh, W_out, b_out, out);
}